// round 2
// baseline (speedup 1.0000x reference)
#include <cuda_runtime.h>
#include <cuda_bf16.h>
#include <math.h>

#define BS   16384
#define DIN  32
#define NQ   16
#define HID  512
#define G4   4          // samples per CTA in K4

// ---------------- scratch (static __device__ — allocation-free) ----------------
__device__ float g_s1[BS * HID];
__device__ float g_h1[BS * HID];
__device__ float g_d2[BS * HID];
__device__ float g_u2[BS * HID];
__device__ float g_g1[BS * HID];
__device__ float g_A [BS * NQ * NQ];
__device__ float g_rhs[BS * NQ];

// ---------------- f32x2 helpers ----------------
__device__ __forceinline__ void fma2(unsigned long long& d, unsigned long long a, unsigned long long b) {
    asm("fma.rn.f32x2 %0, %1, %2, %0;" : "+l"(d) : "l"(a), "l"(b));
}
__device__ __forceinline__ unsigned long long pack2(float v) {
    unsigned long long r;
    asm("mov.b64 %0, {%1, %1};" : "=l"(r) : "f"(v));
    return r;
}
__device__ __forceinline__ float2 unpack2(unsigned long long v) {
    float2 r;
    asm("mov.b64 {%0, %1}, %2;" : "=f"(r.x), "=f"(r.y) : "l"(v));
    return r;
}

// ---------------- K1: z1 = x@W1 + b1 -> s1, h1 ----------------
#define K1_SMEM ((32*512 + 256) * 4)
__global__ __launch_bounds__(256) void k1_layer1(const float* __restrict__ x,
                                                 const float* __restrict__ W1,
                                                 const float* __restrict__ b1) {
    extern __shared__ float sm1[];
    float* W1s = sm1;             // 32*512
    float* xs  = sm1 + 32 * 512;  // 8*32
    int tid = threadIdx.x;
    int b0  = blockIdx.x * 8;

    for (int idx = tid; idx < 32 * 512; idx += 256) W1s[idx] = W1[idx];
    xs[tid] = x[b0 * 32 + tid];
    __syncthreads();

    for (int q = 0; q < 16; ++q) {
        int idx = q * 256 + tid;
        int b = idx >> 9, k = idx & 511;
        float acc = b1[k];
        const float* xr = xs + b * 32;
#pragma unroll
        for (int j = 0; j < 32; ++j) acc = fmaf(xr[j], W1s[j * 512 + k], acc);
        float s = 1.f / (1.f + expf(-acc));
        float h = fmaxf(acc, 0.f) + log1pf(expf(-fabsf(acc)));
        int gi = (b0 + b) * 512 + k;
        g_s1[gi] = s;
        g_h1[gi] = h;
    }
}

// ---------------- K2: z2 = h1@W2 + b2 -> d2, u2 ----------------
__global__ __launch_bounds__(256) void k2_layer2(const float* __restrict__ W2,
                                                 const float* __restrict__ b2,
                                                 const float* __restrict__ W3) {
    __shared__ __align__(16) float As[64][17];
    __shared__ __align__(16) float Bs[16][64];
    int tid = threadIdx.x;
    int b0 = blockIdx.x * 64;
    int m0 = blockIdx.y * 64;
    int ty = tid >> 4, tx = tid & 15;
    float acc[4][4] = {};

    for (int k0 = 0; k0 < HID; k0 += 16) {
        __syncthreads();
#pragma unroll
        for (int r = 0; r < 4; ++r) {
            int idx = tid + r * 256;
            As[idx >> 4][idx & 15] = g_h1[(b0 + (idx >> 4)) * HID + k0 + (idx & 15)];
        }
#pragma unroll
        for (int r = 0; r < 4; ++r) {
            int idx = tid + r * 256;
            Bs[idx >> 6][idx & 63] = W2[(k0 + (idx >> 6)) * HID + m0 + (idx & 63)];
        }
        __syncthreads();
#pragma unroll
        for (int kk = 0; kk < 16; ++kk) {
            float4 bv = *reinterpret_cast<const float4*>(&Bs[kk][tx * 4]);
            float a0 = As[ty * 4 + 0][kk], a1 = As[ty * 4 + 1][kk];
            float a2 = As[ty * 4 + 2][kk], a3 = As[ty * 4 + 3][kk];
            acc[0][0] += a0 * bv.x; acc[0][1] += a0 * bv.y; acc[0][2] += a0 * bv.z; acc[0][3] += a0 * bv.w;
            acc[1][0] += a1 * bv.x; acc[1][1] += a1 * bv.y; acc[1][2] += a1 * bv.z; acc[1][3] += a1 * bv.w;
            acc[2][0] += a2 * bv.x; acc[2][1] += a2 * bv.y; acc[2][2] += a2 * bv.z; acc[2][3] += a2 * bv.w;
            acc[3][0] += a3 * bv.x; acc[3][1] += a3 * bv.y; acc[3][2] += a3 * bv.z; acc[3][3] += a3 * bv.w;
        }
    }
#pragma unroll
    for (int i = 0; i < 4; ++i) {
        int b = b0 + ty * 4 + i;
#pragma unroll
        for (int j = 0; j < 4; ++j) {
            int m = m0 + tx * 4 + j;
            float z = acc[i][j] + b2[m];
            float s = 1.f / (1.f + expf(-z));
            float w3v = W3[m];
            g_d2[b * HID + m] = s * (1.f - s) * w3v;
            g_u2[b * HID + m] = s * w3v;
        }
    }
}

// ---------------- K3: g1 = u2 @ W2^T ----------------
__global__ __launch_bounds__(256) void k3_g1(const float* __restrict__ W2) {
    __shared__ float As[64][17];
    __shared__ float Bs[16][68];
    int tid = threadIdx.x;
    int b0  = blockIdx.x * 64;
    int k00 = blockIdx.y * 64;
    int ty = tid >> 4, tx = tid & 15;
    float acc[4][4] = {};

    for (int m0 = 0; m0 < HID; m0 += 16) {
        __syncthreads();
#pragma unroll
        for (int r = 0; r < 4; ++r) {
            int idx = tid + r * 256;
            As[idx >> 4][idx & 15] = g_u2[(b0 + (idx >> 4)) * HID + m0 + (idx & 15)];
        }
#pragma unroll
        for (int r = 0; r < 4; ++r) {
            int idx = tid + r * 256;
            Bs[idx & 15][idx >> 4] = W2[(k00 + (idx >> 4)) * HID + m0 + (idx & 15)];
        }
        __syncthreads();
#pragma unroll
        for (int mm = 0; mm < 16; ++mm) {
            float a0 = As[ty * 4 + 0][mm], a1 = As[ty * 4 + 1][mm];
            float a2 = As[ty * 4 + 2][mm], a3 = As[ty * 4 + 3][mm];
            float v0 = Bs[mm][tx * 4 + 0], v1 = Bs[mm][tx * 4 + 1];
            float v2 = Bs[mm][tx * 4 + 2], v3 = Bs[mm][tx * 4 + 3];
            acc[0][0] += a0 * v0; acc[0][1] += a0 * v1; acc[0][2] += a0 * v2; acc[0][3] += a0 * v3;
            acc[1][0] += a1 * v0; acc[1][1] += a1 * v1; acc[1][2] += a1 * v2; acc[1][3] += a1 * v3;
            acc[2][0] += a2 * v0; acc[2][1] += a2 * v1; acc[2][2] += a2 * v2; acc[2][3] += a2 * v3;
            acc[3][0] += a3 * v0; acc[3][1] += a3 * v1; acc[3][2] += a3 * v2; acc[3][3] += a3 * v3;
        }
    }
#pragma unroll
    for (int i = 0; i < 4; ++i) {
        int b = b0 + ty * 4 + i;
#pragma unroll
        for (int j = 0; j < 4; ++j)
            g_g1[b * HID + k00 + tx * 4 + j] = acc[i][j];
    }
}

// ---------------- K4: Q-GEMM + Hessian assembly (heavy) ----------------
#define K4_FLOATS (512*33 + 512*32 + 4*4*512 + 4*32*33 + 4*16*33 + 64 + 64)
#define K4_SMEM   (K4_FLOATS * 4)

__global__ __launch_bounds__(256, 1) void k4_hess(const float* __restrict__ x,
                                                  const float* __restrict__ W1,
                                                  const float* __restrict__ W2) {
    extern __shared__ float sm4[];
    float* W1T  = sm4;                     // [k*33 + j]
    float* W2t  = W1T + 512 * 33;          // [k*32 + m]
    float* s1s  = W2t + 512 * 32;          // [b*512 + k]
    float* d1s  = s1s + 4 * 512;
    float* d2s  = d1s + 4 * 512;
    float* u1s  = d2s + 4 * 512;
    float* Qs   = u1s + 4 * 512;           // [(b*32 + j)*33 + m]
    float* Hs   = Qs + 4 * 32 * 33;        // [(b*16 + i')*33 + j]
    float* jacs = Hs + 4 * 16 * 33;        // [b*16 + i']
    float* qds  = jacs + 64;               // [b*16 + j']

    int tid = threadIdx.x;
    int b0  = blockIdx.x * G4;

    // prologue loads
    for (int idx = tid; idx < 32 * 512; idx += 256) {
        int j = idx >> 9, k = idx & 511;
        W1T[k * 33 + j] = W1[idx];
    }
    for (int idx = tid; idx < G4 * 512; idx += 256) {
        int b = idx >> 9, k = idx & 511;
        int gi = (b0 + b) * 512 + k;
        float s = g_s1[gi];
        float g = g_g1[gi];
        s1s[idx] = s;
        u1s[idx] = s * g;
        d1s[idx] = s * (1.f - s) * g;
        d2s[idx] = g_d2[gi];
    }
    if (tid < 64) qds[tid] = x[(b0 + (tid >> 4)) * 32 + 16 + (tid & 15)];
    __syncthreads();

    if (tid < 64) {   // jacobian rows 0..15 per sample
        int bb = tid >> 4, ip = tid & 15;
        float a = 0.f;
        for (int k = 0; k < 512; ++k) a = fmaf(W1T[k * 33 + ip], u1s[bb * 512 + k], a);
        jacs[tid] = a;
    }

    int bq  = tid >> 6;
    int t64 = tid & 63;
    int rg  = t64 >> 2;
    int cg  = t64 & 3;
    const float* w1pa = W1T + rg;
    const float* w1pb = W1T + rg + 16;
    const float* s1p  = s1s + bq * 512;
    const float* d2b  = d2s + bq * 512;
    int j0 = cg * 8;

    float hacc[8] = {0, 0, 0, 0, 0, 0, 0, 0};

    for (int mt = 0; mt < 16; ++mt) {
        int m0 = mt * 32;
        __syncthreads();
        for (int idx = tid; idx < 512 * 8; idx += 256) {
            int k = idx >> 3;
            int m = (idx & 7) << 2;
            *reinterpret_cast<float4*>(&W2t[k * 32 + m]) =
                *reinterpret_cast<const float4*>(&W2[k * 512 + m0 + m]);
        }
        __syncthreads();

        unsigned long long a0 = 0, a1 = 0, a2 = 0, a3 = 0;
        unsigned long long c0 = 0, c1 = 0, c2 = 0, c3 = 0;
        const float* wt = W2t + cg * 8;
#pragma unroll 4
        for (int k = 0; k < 512; ++k) {
            float sv = s1p[k];
            float pa = w1pa[k * 33] * sv;
            float pb = w1pb[k * 33] * sv;
            unsigned long long pa2 = pack2(pa), pb2 = pack2(pb);
            ulonglong2 w01 = *reinterpret_cast<const ulonglong2*>(wt + k * 32);
            ulonglong2 w23 = *reinterpret_cast<const ulonglong2*>(wt + k * 32 + 4);
            fma2(a0, w01.x, pa2); fma2(a1, w01.y, pa2);
            fma2(a2, w23.x, pa2); fma2(a3, w23.y, pa2);
            fma2(c0, w01.x, pb2); fma2(c1, w01.y, pb2);
            fma2(c2, w23.x, pb2); fma2(c3, w23.y, pb2);
        }
        {
            float* qa = Qs + (bq * 32 + rg) * 33 + j0;
            float* qb = Qs + (bq * 32 + rg + 16) * 33 + j0;
            float2 f;
            f = unpack2(a0); qa[0] = f.x; qa[1] = f.y;
            f = unpack2(a1); qa[2] = f.x; qa[3] = f.y;
            f = unpack2(a2); qa[4] = f.x; qa[5] = f.y;
            f = unpack2(a3); qa[6] = f.x; qa[7] = f.y;
            f = unpack2(c0); qb[0] = f.x; qb[1] = f.y;
            f = unpack2(c1); qb[2] = f.x; qb[3] = f.y;
            f = unpack2(c2); qb[4] = f.x; qb[5] = f.y;
            f = unpack2(c3); qb[6] = f.x; qb[7] = f.y;
        }
        __syncthreads();
        {
            const float* qi  = Qs + (bq * 32 + 16 + rg) * 33;
            const float* qjb = Qs + (bq * 32 + j0) * 33;
            const float* dp  = d2b + m0;
#pragma unroll 4
            for (int m = 0; m < 32; ++m) {
                float t = qi[m] * dp[m];
#pragma unroll
                for (int c = 0; c < 8; ++c) hacc[c] = fmaf(t, qjb[c * 33 + m], hacc[c]);
            }
        }
    }

    // H1 diagonal-layer term
    {
        const float* d1b = d1s + bq * 512;
#pragma unroll 2
        for (int k = 0; k < 512; ++k) {
            float t = W1T[k * 33 + 16 + rg] * d1b[k];
            const float* wj = W1T + k * 33 + j0;
#pragma unroll
            for (int c = 0; c < 8; ++c) hacc[c] = fmaf(t, wj[c], hacc[c]);
        }
    }

    {
        float* hr = Hs + (bq * 16 + rg) * 33 + j0;
#pragma unroll
        for (int c = 0; c < 8; ++c) hr[c] = hacc[c];
    }
    __syncthreads();

    // epilogue: A and rhs
    if (tid < 64) {
        int bb = tid >> 4, ip = tid & 15;
        const float* hr = Hs + (bb * 16 + ip) * 33;
        size_t ob = (size_t)(b0 + bb) * 16 + ip;
        float* Ar = g_A + ob * 16;
#pragma unroll
        for (int j = 0; j < 16; ++j) Ar[j] = hr[16 + j];
        float rv = jacs[tid];
#pragma unroll
        for (int j = 0; j < 16; ++j) rv = fmaf(-hr[j], qds[bb * 16 + j], rv);
        g_rhs[ob] = rv;
    }
}

// ---------------- K5: per-sample symmetric Jacobi eigensolver + pinv semantics ----------------
// 16 samples per 256-thread CTA; 16 lanes per sample; A,V in smem.
// Matches jnp.linalg.pinv(rcond=None): cutoff = 10*16*eps_f32 * max|lambda|; drop |lambda| <= cutoff.
#define PINV_RCOND 1.9073486e-5f
#define JACOBI_SWEEPS 8

__global__ __launch_bounds__(256) void k5_pinv(const float* __restrict__ x,
                                               float* __restrict__ out) {
    __shared__ float sm[16 * 592];   // per sample: A 16*17=272 | V 16*17=272 | y 16 | r 32(pad)
    int tid = threadIdx.x;
    int sI = tid >> 4;       // sample within CTA
    int r  = tid & 15;       // lane/row within sample
    int b  = blockIdx.x * 16 + sI;

    float* As = sm + sI * 592;
    float* Vs = As + 272;
    float* ys = Vs + 272;
    float* rs = ys + 16;

    // load A (row r), V = I, rhs
    {
        const float* Ag = g_A + ((size_t)b * 16 + r) * 16;
#pragma unroll
        for (int j = 0; j < 16; ++j) {
            As[r * 17 + j] = Ag[j];
            Vs[r * 17 + j] = (r == j) ? 1.f : 0.f;
        }
        rs[r] = g_rhs[(size_t)b * 16 + r];
    }
    __syncwarp();

    for (int sweep = 0; sweep < JACOBI_SWEEPS; ++sweep) {
        for (int p = 0; p < 15; ++p) {
            for (int q = p + 1; q < 16; ++q) {
                // ---- read phase (all lanes) ----
                float apq = As[p * 17 + q];
                float app = As[p * 17 + p];
                float aqq = As[q * 17 + q];
                float aip = As[r * 17 + p];
                float aiq = As[r * 17 + q];
                float vip = Vs[r * 17 + p];
                float viq = Vs[r * 17 + q];
                __syncwarp();
                // ---- rotation params (uniform per sample; identity when apq==0) ----
                float tau = (aqq - app) / (2.f * apq);
                float tt  = copysignf(1.f, tau) / (fabsf(tau) + sqrtf(fmaf(tau, tau, 1.f)));
                float t   = (fabsf(apq) > 0.f) ? tt : 0.f;
                float c   = 1.f / sqrtf(fmaf(t, t, 1.f));
                float s   = t * c;
                // ---- write phase ----
                float nip = c * aip - s * aiq;
                float niq = s * aip + c * aiq;
                if (r != p && r != q) {
                    As[r * 17 + p] = nip; As[p * 17 + r] = nip;
                    As[r * 17 + q] = niq; As[q * 17 + r] = niq;
                }
                if (r == p) {
                    As[p * 17 + p] = app - t * apq;
                    As[q * 17 + q] = aqq + t * apq;
                    As[p * 17 + q] = 0.f;
                    As[q * 17 + p] = 0.f;
                }
                Vs[r * 17 + p] = c * vip - s * viq;
                Vs[r * 17 + q] = s * vip + c * viq;
                __syncwarp();
            }
        }
    }

    // ---- pinv apply ----
    float lam = As[r * 17 + r];
    float m = fabsf(lam);
#pragma unroll
    for (int off = 8; off > 0; off >>= 1)
        m = fmaxf(m, __shfl_xor_sync(0xffffffffu, m, off));
    float cutoff = PINV_RCOND * m;

    // y_r = sum_j V[j][r] * rhs_j
    float acc = 0.f;
#pragma unroll
    for (int j = 0; j < 16; ++j) acc = fmaf(Vs[j * 17 + r], rs[j], acc);
    ys[r] = (fabsf(lam) > cutoff) ? (acc / lam) : 0.f;
    __syncwarp();

    // qdd_r = sum_j V[r][j] * y_j
    float qdd = 0.f;
#pragma unroll
    for (int j = 0; j < 16; ++j) qdd = fmaf(Vs[r * 17 + j], ys[j], qdd);

    out[(size_t)b * 32 + 16 + r] = qdd;
    out[(size_t)b * 32 + r]      = x[(size_t)b * 32 + 16 + r];
}

// ---------------- launch ----------------
extern "C" void kernel_launch(void* const* d_in, const int* in_sizes, int n_in,
                              void* d_out, int out_size) {
    const float* x  = (const float*)d_in[0];
    const float* W1 = (const float*)d_in[1];
    const float* b1 = (const float*)d_in[2];
    const float* W2 = (const float*)d_in[3];
    const float* b2 = (const float*)d_in[4];
    const float* W3 = (const float*)d_in[5];
    float* out = (float*)d_out;
    (void)in_sizes; (void)n_in; (void)out_size;

    cudaFuncSetAttribute(k1_layer1, cudaFuncAttributeMaxDynamicSharedMemorySize, K1_SMEM);
    cudaFuncSetAttribute(k4_hess,   cudaFuncAttributeMaxDynamicSharedMemorySize, K4_SMEM);

    k1_layer1<<<BS / 8, 256, K1_SMEM>>>(x, W1, b1);
    k2_layer2<<<dim3(BS / 64, HID / 64), 256>>>(W2, b2, W3);
    k3_g1<<<dim3(BS / 64, HID / 64), 256>>>(W2);
    k4_hess<<<BS / G4, 256, K4_SMEM>>>(x, W1, W2);
    k5_pinv<<<BS / 16, 256>>>(x, out);
}

// round 3
// speedup vs baseline: 1.7468x; 1.7468x over previous
#include <cuda_runtime.h>
#include <cuda_bf16.h>
#include <math.h>

#define BS   16384
#define NQ   16
#define HID  512

// ---------------- scratch (static __device__ — allocation-free) ----------------
__device__ float g_s1[BS * HID];
__device__ float g_h1[BS * HID];   // h1, later reused as u1 = s1*g1 (written by K3)
__device__ float g_d2[BS * HID];
__device__ float g_u2[BS * HID];
__device__ float g_g1[BS * HID];   // holds d1 = s1*(1-s1)*g1 (written by K3)
__device__ float g_p [BS * HID];   // p_k = sum_{j<16} W1[j,k]*qd_j
__device__ float g_w [BS * HID];   // w_m = d2_m * v_m,  v = (s1*p) @ W2
__device__ float g_A [BS * NQ * NQ];
__device__ float g_rhs[BS * NQ];

// ---------------- f32x2 helpers ----------------
__device__ __forceinline__ void fma2(unsigned long long& d, unsigned long long a, unsigned long long b) {
    asm("fma.rn.f32x2 %0, %1, %2, %0;" : "+l"(d) : "l"(a), "l"(b));
}
__device__ __forceinline__ unsigned long long mul2(unsigned long long a, unsigned long long b) {
    unsigned long long d;
    asm("mul.rn.f32x2 %0, %1, %2;" : "=l"(d) : "l"(a), "l"(b));
    return d;
}
__device__ __forceinline__ unsigned long long pack2(float v) {
    unsigned long long r;
    asm("mov.b64 %0, {%1, %1};" : "=l"(r) : "f"(v));
    return r;
}
__device__ __forceinline__ float2 unpack2(unsigned long long v) {
    float2 r;
    asm("mov.b64 {%0, %1}, %2;" : "=f"(r.x), "=f"(r.y) : "l"(v));
    return r;
}

// ---------------- K1: z1 = x@W1 + b1 -> s1, h1 ; p = W1_top^T qd ----------------
#define K1_SMEM ((32*512 + 256) * 4)
__global__ __launch_bounds__(256) void k1_layer1(const float* __restrict__ x,
                                                 const float* __restrict__ W1,
                                                 const float* __restrict__ b1) {
    extern __shared__ float sm1[];
    float* W1s = sm1;             // 32*512
    float* xs  = sm1 + 32 * 512;  // 8*32
    int tid = threadIdx.x;
    int b0  = blockIdx.x * 8;

    for (int idx = tid; idx < 32 * 512; idx += 256) W1s[idx] = W1[idx];
    xs[tid] = x[b0 * 32 + tid];
    __syncthreads();

    for (int q = 0; q < 16; ++q) {
        int idx = q * 256 + tid;
        int b = idx >> 9, k = idx & 511;
        float acc = b1[k];
        float accp = 0.f;
        const float* xr = xs + b * 32;
#pragma unroll
        for (int j = 0; j < 32; ++j) {
            float w = W1s[j * 512 + k];
            acc = fmaf(xr[j], w, acc);
            if (j < 16) accp = fmaf(xr[16 + j], w, accp);
        }
        float s = 1.f / (1.f + expf(-acc));
        float h = fmaxf(acc, 0.f) + log1pf(expf(-fabsf(acc)));
        int gi = (b0 + b) * 512 + k;
        g_s1[gi] = s;
        g_h1[gi] = h;
        g_p[gi]  = accp;
    }
}

// ---------------- K2: z2 = h1@W2 + b2 -> d2, u2 ----------------
__global__ __launch_bounds__(256) void k2_layer2(const float* __restrict__ W2,
                                                 const float* __restrict__ b2,
                                                 const float* __restrict__ W3) {
    __shared__ __align__(16) float As[64][17];
    __shared__ __align__(16) float Bs[16][64];
    int tid = threadIdx.x;
    int b0 = blockIdx.x * 64;
    int m0 = blockIdx.y * 64;
    int ty = tid >> 4, tx = tid & 15;
    float acc[4][4] = {};

    for (int k0 = 0; k0 < HID; k0 += 16) {
        __syncthreads();
#pragma unroll
        for (int r = 0; r < 4; ++r) {
            int idx = tid + r * 256;
            As[idx >> 4][idx & 15] = g_h1[(b0 + (idx >> 4)) * HID + k0 + (idx & 15)];
        }
#pragma unroll
        for (int r = 0; r < 4; ++r) {
            int idx = tid + r * 256;
            Bs[idx >> 6][idx & 63] = W2[(k0 + (idx >> 6)) * HID + m0 + (idx & 63)];
        }
        __syncthreads();
#pragma unroll
        for (int kk = 0; kk < 16; ++kk) {
            float4 bv = *reinterpret_cast<const float4*>(&Bs[kk][tx * 4]);
            float a0 = As[ty * 4 + 0][kk], a1 = As[ty * 4 + 1][kk];
            float a2 = As[ty * 4 + 2][kk], a3 = As[ty * 4 + 3][kk];
            acc[0][0] += a0 * bv.x; acc[0][1] += a0 * bv.y; acc[0][2] += a0 * bv.z; acc[0][3] += a0 * bv.w;
            acc[1][0] += a1 * bv.x; acc[1][1] += a1 * bv.y; acc[1][2] += a1 * bv.z; acc[1][3] += a1 * bv.w;
            acc[2][0] += a2 * bv.x; acc[2][1] += a2 * bv.y; acc[2][2] += a2 * bv.z; acc[2][3] += a2 * bv.w;
            acc[3][0] += a3 * bv.x; acc[3][1] += a3 * bv.y; acc[3][2] += a3 * bv.z; acc[3][3] += a3 * bv.w;
        }
    }
#pragma unroll
    for (int i = 0; i < 4; ++i) {
        int b = b0 + ty * 4 + i;
#pragma unroll
        for (int j = 0; j < 4; ++j) {
            int m = m0 + tx * 4 + j;
            float z = acc[i][j] + b2[m];
            float s = 1.f / (1.f + expf(-z));
            float w3v = W3[m];
            g_d2[b * HID + m] = s * (1.f - s) * w3v;
            g_u2[b * HID + m] = s * w3v;
        }
    }
}

// ---------------- K3: g1 = u2 @ W2^T -> write u1 (into g_h1) and d1 (into g_g1) ----------------
__global__ __launch_bounds__(256) void k3_g1(const float* __restrict__ W2) {
    __shared__ float As[64][17];
    __shared__ float Bs[16][68];
    int tid = threadIdx.x;
    int b0  = blockIdx.x * 64;
    int k00 = blockIdx.y * 64;
    int ty = tid >> 4, tx = tid & 15;
    float acc[4][4] = {};

    for (int m0 = 0; m0 < HID; m0 += 16) {
        __syncthreads();
#pragma unroll
        for (int r = 0; r < 4; ++r) {
            int idx = tid + r * 256;
            As[idx >> 4][idx & 15] = g_u2[(b0 + (idx >> 4)) * HID + m0 + (idx & 15)];
        }
#pragma unroll
        for (int r = 0; r < 4; ++r) {
            int idx = tid + r * 256;
            Bs[idx & 15][idx >> 4] = W2[(k00 + (idx >> 4)) * HID + m0 + (idx & 15)];
        }
        __syncthreads();
#pragma unroll
        for (int mm = 0; mm < 16; ++mm) {
            float a0 = As[ty * 4 + 0][mm], a1 = As[ty * 4 + 1][mm];
            float a2 = As[ty * 4 + 2][mm], a3 = As[ty * 4 + 3][mm];
            float v0 = Bs[mm][tx * 4 + 0], v1 = Bs[mm][tx * 4 + 1];
            float v2 = Bs[mm][tx * 4 + 2], v3 = Bs[mm][tx * 4 + 3];
            acc[0][0] += a0 * v0; acc[0][1] += a0 * v1; acc[0][2] += a0 * v2; acc[0][3] += a0 * v3;
            acc[1][0] += a1 * v0; acc[1][1] += a1 * v1; acc[1][2] += a1 * v2; acc[1][3] += a1 * v3;
            acc[2][0] += a2 * v0; acc[2][1] += a2 * v1; acc[2][2] += a2 * v2; acc[2][3] += a2 * v3;
            acc[3][0] += a3 * v0; acc[3][1] += a3 * v1; acc[3][2] += a3 * v2; acc[3][3] += a3 * v3;
        }
    }
#pragma unroll
    for (int i = 0; i < 4; ++i) {
        int b = b0 + ty * 4 + i;
#pragma unroll
        for (int j = 0; j < 4; ++j) {
            int gi = b * HID + k00 + tx * 4 + j;
            float g = acc[i][j];
            float s = g_s1[gi];
            g_h1[gi] = s * g;                 // u1
            g_g1[gi] = s * (1.f - s) * g;     // d1
        }
    }
}

// ---------------- K3b: v = (s1*p) @ W2 ; w = d2*v ----------------
__global__ __launch_bounds__(256) void k3b_v(const float* __restrict__ W2) {
    __shared__ __align__(16) float As[64][17];
    __shared__ __align__(16) float Bs[16][64];
    int tid = threadIdx.x;
    int b0 = blockIdx.x * 64;
    int m0 = blockIdx.y * 64;
    int ty = tid >> 4, tx = tid & 15;
    float acc[4][4] = {};

    for (int k0 = 0; k0 < HID; k0 += 16) {
        __syncthreads();
#pragma unroll
        for (int r = 0; r < 4; ++r) {
            int idx = tid + r * 256;
            int gi = (b0 + (idx >> 4)) * HID + k0 + (idx & 15);
            As[idx >> 4][idx & 15] = g_s1[gi] * g_p[gi];
        }
#pragma unroll
        for (int r = 0; r < 4; ++r) {
            int idx = tid + r * 256;
            Bs[idx >> 6][idx & 63] = W2[(k0 + (idx >> 6)) * HID + m0 + (idx & 63)];
        }
        __syncthreads();
#pragma unroll
        for (int kk = 0; kk < 16; ++kk) {
            float4 bv = *reinterpret_cast<const float4*>(&Bs[kk][tx * 4]);
            float a0 = As[ty * 4 + 0][kk], a1 = As[ty * 4 + 1][kk];
            float a2 = As[ty * 4 + 2][kk], a3 = As[ty * 4 + 3][kk];
            acc[0][0] += a0 * bv.x; acc[0][1] += a0 * bv.y; acc[0][2] += a0 * bv.z; acc[0][3] += a0 * bv.w;
            acc[1][0] += a1 * bv.x; acc[1][1] += a1 * bv.y; acc[1][2] += a1 * bv.z; acc[1][3] += a1 * bv.w;
            acc[2][0] += a2 * bv.x; acc[2][1] += a2 * bv.y; acc[2][2] += a2 * bv.z; acc[2][3] += a2 * bv.w;
            acc[3][0] += a3 * bv.x; acc[3][1] += a3 * bv.y; acc[3][2] += a3 * bv.z; acc[3][3] += a3 * bv.w;
        }
    }
#pragma unroll
    for (int i = 0; i < 4; ++i) {
        int b = b0 + ty * 4 + i;
#pragma unroll
        for (int j = 0; j < 4; ++j) {
            int m = m0 + tx * 4 + j;
            g_w[b * HID + m] = acc[i][j] * g_d2[b * HID + m];
        }
    }
}

// ---------------- K_jac: rhs_base = jac_top - W1_lo*(d1*p) ----------------
#define KJ_SMEM (32 * 513 * 4)
__global__ __launch_bounds__(256) void k_jac(const float* __restrict__ W1) {
    extern __shared__ float W1s[];   // [j*513 + k]
    int tid = threadIdx.x;
    int b0  = blockIdx.x * 8;
    for (int idx = tid; idx < 32 * 512; idx += 256)
        W1s[(idx >> 9) * 513 + (idx & 511)] = W1[idx];
    __syncthreads();

    int s = tid >> 5, lane = tid & 31;
    int i = lane & 15, half = lane >> 4;
    int b = b0 + s;
    float accJ = 0.f, accR = 0.f;
    const float* u1p = g_h1 + (size_t)b * 512;
    const float* d1p = g_g1 + (size_t)b * 512;
    const float* pp  = g_p  + (size_t)b * 512;
    for (int t = 0; t < 256; ++t) {
        int k = half * 256 + t;
        accJ = fmaf(W1s[i * 513 + k], u1p[k], accJ);
        accR = fmaf(W1s[(16 + i) * 513 + k], d1p[k] * pp[k], accR);
    }
    accJ += __shfl_xor_sync(0xffffffffu, accJ, 16);
    accR += __shfl_xor_sync(0xffffffffu, accR, 16);
    if (lane < 16) g_rhs[(size_t)b * 16 + i] = accJ - accR;
}

// ---------------- K4: Q_lo GEMM + A assembly + rhs2 ----------------
// smem floats: W1D 512*32 | W2kt 128*64 | s1s,d2s,ws,d1s 8*512 each | Qs 8*16*65
#define K4_FLOATS (512*32 + 128*64 + 4*8*512 + 8*16*65)
#define K4_SMEM   (K4_FLOATS * 4)

__global__ __launch_bounds__(256, 1) void k4_hess(const float* __restrict__ W1,
                                                  const float* __restrict__ W2) {
    extern __shared__ float sm4[];
    float* W1D  = sm4;                 // [k*32 + 2*i(+1)] duplicated rows 16..31 of W1
    float* W2kt = W1D + 512 * 32;      // [k*64 + m]
    float* s1s  = W2kt + 128 * 64;
    float* d2s  = s1s + 8 * 512;
    float* ws   = d2s + 8 * 512;
    float* d1s  = ws  + 8 * 512;
    float* Qs   = d1s + 8 * 512;       // [(s*16+i)*65 + m]

    int tid = threadIdx.x;
    int b0  = blockIdx.x * 8;

    // prologue: duplicated W1 lo rows
    for (int idx = tid; idx < 16 * 512; idx += 256) {
        int i = idx >> 9, k = idx & 511;
        float v = W1[(16 + i) * 512 + k];
        W1D[k * 32 + 2 * i]     = v;
        W1D[k * 32 + 2 * i + 1] = v;
    }
    // per-sample vectors (float4, contiguous 8*512 region)
    {
        const float4* s4 = (const float4*)(g_s1 + (size_t)b0 * 512);
        const float4* d4 = (const float4*)(g_d2 + (size_t)b0 * 512);
        const float4* w4 = (const float4*)(g_w  + (size_t)b0 * 512);
        const float4* e4 = (const float4*)(g_g1 + (size_t)b0 * 512);
        for (int idx = tid; idx < 1024; idx += 256) {
            ((float4*)s1s)[idx] = s4[idx];
            ((float4*)d2s)[idx] = d4[idx];
            ((float4*)ws)[idx]  = w4[idx];
            ((float4*)d1s)[idx] = e4[idx];
        }
    }

    int s = tid >> 5, lane = tid & 31;
    int rg = lane >> 3, cg = lane & 7;
    const float* s1p = s1s + s * 512;

    float Aacc[4][2] = {};
    float rhs2[4] = {0.f, 0.f, 0.f, 0.f};

    for (int mt = 0; mt < 8; ++mt) {
        int m0 = mt * 64;
        unsigned long long Qa[4][4] = {};
        for (int kt = 0; kt < 4; ++kt) {
            int k0 = kt * 128;
            __syncthreads();
            for (int li = tid; li < 2048; li += 256) {
                int row = li >> 4, c4 = li & 15;
                ((float4*)W2kt)[row * 16 + c4] =
                    ((const float4*)(W2 + (size_t)(k0 + row) * 512 + m0))[c4];
            }
            __syncthreads();
#pragma unroll 4
            for (int k = 0; k < 128; ++k) {
                float sv = s1p[k0 + k];
                unsigned long long sv2 = pack2(sv);
                const ulonglong2* wd = (const ulonglong2*)(W1D + (k0 + k) * 32 + 8 * rg);
                ulonglong2 w1a = wd[0];     // rows 4rg, 4rg+1 (dup)
                ulonglong2 w1b = wd[1];     // rows 4rg+2, 4rg+3 (dup)
                unsigned long long p0 = mul2(w1a.x, sv2);
                unsigned long long p1 = mul2(w1a.y, sv2);
                unsigned long long p2 = mul2(w1b.x, sv2);
                unsigned long long p3 = mul2(w1b.y, sv2);
                const ulonglong2* wr = (const ulonglong2*)(W2kt + k * 64 + cg * 8);
                ulonglong2 w2a = wr[0];
                ulonglong2 w2b = wr[1];
                fma2(Qa[0][0], w2a.x, p0); fma2(Qa[0][1], w2a.y, p0);
                fma2(Qa[0][2], w2b.x, p0); fma2(Qa[0][3], w2b.y, p0);
                fma2(Qa[1][0], w2a.x, p1); fma2(Qa[1][1], w2a.y, p1);
                fma2(Qa[1][2], w2b.x, p1); fma2(Qa[1][3], w2b.y, p1);
                fma2(Qa[2][0], w2a.x, p2); fma2(Qa[2][1], w2a.y, p2);
                fma2(Qa[2][2], w2b.x, p2); fma2(Qa[2][3], w2b.y, p2);
                fma2(Qa[3][0], w2a.x, p3); fma2(Qa[3][1], w2a.y, p3);
                fma2(Qa[3][2], w2b.x, p3); fma2(Qa[3][3], w2b.y, p3);
            }
        }
        // write Q tile to smem
#pragma unroll
        for (int rr = 0; rr < 4; ++rr) {
            float* q = Qs + (s * 16 + 4 * rg + rr) * 65 + cg * 8;
            float2 f;
            f = unpack2(Qa[rr][0]); q[0] = f.x; q[1] = f.y;
            f = unpack2(Qa[rr][1]); q[2] = f.x; q[3] = f.y;
            f = unpack2(Qa[rr][2]); q[4] = f.x; q[5] = f.y;
            f = unpack2(Qa[rr][3]); q[6] = f.x; q[7] = f.y;
        }
        __syncthreads();
        // A accumulation + rhs2 for this m-tile
        const float* d2p = d2s + s * 512 + m0;
        const float* wp  = ws  + s * 512 + m0;
        const float* qbase = Qs + s * 16 * 65;
#pragma unroll 4
        for (int m = 0; m < 64; ++m) {
            float d2v = d2p[m];
            float wv  = wp[m];
            float qj0 = qbase[(2 * cg) * 65 + m];
            float qj1 = qbase[(2 * cg + 1) * 65 + m];
#pragma unroll
            for (int rr = 0; rr < 4; ++rr) {
                float qi = qbase[(4 * rg + rr) * 65 + m];
                float t = qi * d2v;
                Aacc[rr][0] = fmaf(t, qj0, Aacc[rr][0]);
                Aacc[rr][1] = fmaf(t, qj1, Aacc[rr][1]);
                rhs2[rr] = fmaf(qi, wv, rhs2[rr]);
            }
        }
    }

    // H1 term: A += W1_lo D1 W1_lo^T
    {
        const float* d1p = d1s + s * 512;
#pragma unroll 2
        for (int k = 0; k < 512; ++k) {
            float d1v = d1p[k];
            const float* wk = W1D + k * 32;
            float wj0 = wk[2 * (2 * cg)];
            float wj1 = wk[2 * (2 * cg + 1)];
#pragma unroll
            for (int rr = 0; rr < 4; ++rr) {
                float t = wk[2 * (4 * rg + rr)] * d1v;
                Aacc[rr][0] = fmaf(t, wj0, Aacc[rr][0]);
                Aacc[rr][1] = fmaf(t, wj1, Aacc[rr][1]);
            }
        }
    }

    // epilogue
    int b = b0 + s;
#pragma unroll
    for (int rr = 0; rr < 4; ++rr) {
        int i = 4 * rg + rr;
        float* Ar = g_A + ((size_t)b * 16 + i) * 16;
        Ar[2 * cg]     = Aacc[rr][0];
        Ar[2 * cg + 1] = Aacc[rr][1];
        if (cg == 0) {
            size_t ob = (size_t)b * 16 + i;
            g_rhs[ob] = g_rhs[ob] - rhs2[rr];
        }
    }
}

// ---------------- K5: per-sample symmetric Jacobi eigensolver + pinv semantics ----------------
#define PINV_RCOND 1.9073486e-5f
#define JACOBI_SWEEPS 8

__global__ __launch_bounds__(256) void k5_pinv(const float* __restrict__ x,
                                               float* __restrict__ out) {
    __shared__ float sm[16 * 592];
    int tid = threadIdx.x;
    int sI = tid >> 4;
    int r  = tid & 15;
    int b  = blockIdx.x * 16 + sI;

    float* As = sm + sI * 592;
    float* Vs = As + 272;
    float* ys = Vs + 272;
    float* rs = ys + 16;

    {
        const float* Ag = g_A + ((size_t)b * 16 + r) * 16;
#pragma unroll
        for (int j = 0; j < 16; ++j) {
            As[r * 17 + j] = Ag[j];
            Vs[r * 17 + j] = (r == j) ? 1.f : 0.f;
        }
        rs[r] = g_rhs[(size_t)b * 16 + r];
    }
    __syncwarp();

    for (int sweep = 0; sweep < JACOBI_SWEEPS; ++sweep) {
        for (int p = 0; p < 15; ++p) {
            for (int q = p + 1; q < 16; ++q) {
                float apq = As[p * 17 + q];
                float app = As[p * 17 + p];
                float aqq = As[q * 17 + q];
                float aip = As[r * 17 + p];
                float aiq = As[r * 17 + q];
                float vip = Vs[r * 17 + p];
                float viq = Vs[r * 17 + q];
                __syncwarp();
                float tau = (aqq - app) / (2.f * apq);
                float tt  = copysignf(1.f, tau) / (fabsf(tau) + sqrtf(fmaf(tau, tau, 1.f)));
                float t   = (fabsf(apq) > 0.f) ? tt : 0.f;
                float c   = 1.f / sqrtf(fmaf(t, t, 1.f));
                float s   = t * c;
                float nip = c * aip - s * aiq;
                float niq = s * aip + c * aiq;
                if (r != p && r != q) {
                    As[r * 17 + p] = nip; As[p * 17 + r] = nip;
                    As[r * 17 + q] = niq; As[q * 17 + r] = niq;
                }
                if (r == p) {
                    As[p * 17 + p] = app - t * apq;
                    As[q * 17 + q] = aqq + t * apq;
                    As[p * 17 + q] = 0.f;
                    As[q * 17 + p] = 0.f;
                }
                Vs[r * 17 + p] = c * vip - s * viq;
                Vs[r * 17 + q] = s * vip + c * viq;
                __syncwarp();
            }
        }
    }

    float lam = As[r * 17 + r];
    float m = fabsf(lam);
#pragma unroll
    for (int off = 8; off > 0; off >>= 1)
        m = fmaxf(m, __shfl_xor_sync(0xffffffffu, m, off));
    float cutoff = PINV_RCOND * m;

    float acc = 0.f;
#pragma unroll
    for (int j = 0; j < 16; ++j) acc = fmaf(Vs[j * 17 + r], rs[j], acc);
    ys[r] = (fabsf(lam) > cutoff) ? (acc / lam) : 0.f;
    __syncwarp();

    float qdd = 0.f;
#pragma unroll
    for (int j = 0; j < 16; ++j) qdd = fmaf(Vs[r * 17 + j], ys[j], qdd);

    out[(size_t)b * 32 + 16 + r] = qdd;
    out[(size_t)b * 32 + r]      = x[(size_t)b * 32 + 16 + r];
}

// ---------------- launch ----------------
extern "C" void kernel_launch(void* const* d_in, const int* in_sizes, int n_in,
                              void* d_out, int out_size) {
    const float* x  = (const float*)d_in[0];
    const float* W1 = (const float*)d_in[1];
    const float* b1 = (const float*)d_in[2];
    const float* W2 = (const float*)d_in[3];
    const float* b2 = (const float*)d_in[4];
    const float* W3 = (const float*)d_in[5];
    float* out = (float*)d_out;
    (void)in_sizes; (void)n_in; (void)out_size;

    cudaFuncSetAttribute(k1_layer1, cudaFuncAttributeMaxDynamicSharedMemorySize, K1_SMEM);
    cudaFuncSetAttribute(k_jac,     cudaFuncAttributeMaxDynamicSharedMemorySize, KJ_SMEM);
    cudaFuncSetAttribute(k4_hess,   cudaFuncAttributeMaxDynamicSharedMemorySize, K4_SMEM);

    k1_layer1<<<BS / 8, 256, K1_SMEM>>>(x, W1, b1);
    k2_layer2<<<dim3(BS / 64, HID / 64), 256>>>(W2, b2, W3);
    k3_g1<<<dim3(BS / 64, HID / 64), 256>>>(W2);
    k3b_v<<<dim3(BS / 64, HID / 64), 256>>>(W2);
    k_jac<<<BS / 8, 256, KJ_SMEM>>>(W1);
    k4_hess<<<BS / 8, 256, K4_SMEM>>>(W1, W2);
    k5_pinv<<<BS / 16, 256>>>(x, out);
}

// round 4
// speedup vs baseline: 2.4517x; 1.4035x over previous
#include <cuda_runtime.h>
#include <cuda_bf16.h>
#include <math.h>

#define BS   16384
#define NQ   16
#define HID  512

// ---------------- scratch (static __device__ — allocation-free) ----------------
__device__ float g_s1[BS * HID];
__device__ float g_h1[BS * HID];   // h1; reused as u1 = s1*g1 after K3
__device__ float g_d2[BS * HID];
__device__ float g_u2[BS * HID];
__device__ float g_g1[BS * HID];   // d1 = s1*(1-s1)*g1 after K3
__device__ float g_p [BS * HID];   // p_k = sum_{j<16} W1[j,k]*qd_j
__device__ float g_w [BS * HID];   // w_m = d2_m * v_m,  v = (s1*p) @ W2
__device__ float g_Q [(size_t)BS * 16 * HID];   // Q_lo rows, [ (b*16+i)*512 + m ]
__device__ float g_A [BS * NQ * NQ];
__device__ float g_rhs[BS * NQ];

// ---------------- f32x2 helpers ----------------
__device__ __forceinline__ void fma2(unsigned long long& d, unsigned long long a, unsigned long long b) {
    asm("fma.rn.f32x2 %0, %1, %2, %0;" : "+l"(d) : "l"(a), "l"(b));
}
__device__ __forceinline__ unsigned long long pack2(float v) {
    unsigned long long r;
    asm("mov.b64 %0, {%1, %1};" : "=l"(r) : "f"(v));
    return r;
}
__device__ __forceinline__ float2 unpack2(unsigned long long v) {
    float2 r;
    asm("mov.b64 {%0, %1}, %2;" : "=f"(r.x), "=f"(r.y) : "l"(v));
    return r;
}

// ---------------- K1: z1 = x@W1 + b1 -> s1, h1 ; p = W1_top^T qd ----------------
#define K1_SMEM ((32*512 + 256) * 4)
__global__ __launch_bounds__(256) void k1_layer1(const float* __restrict__ x,
                                                 const float* __restrict__ W1,
                                                 const float* __restrict__ b1) {
    extern __shared__ float sm1[];
    float* W1s = sm1;
    float* xs  = sm1 + 32 * 512;
    int tid = threadIdx.x;
    int b0  = blockIdx.x * 8;

    for (int idx = tid; idx < 32 * 512; idx += 256) W1s[idx] = W1[idx];
    xs[tid] = x[b0 * 32 + tid];
    __syncthreads();

    for (int q = 0; q < 16; ++q) {
        int idx = q * 256 + tid;
        int b = idx >> 9, k = idx & 511;
        float acc = b1[k];
        float accp = 0.f;
        const float* xr = xs + b * 32;
#pragma unroll
        for (int j = 0; j < 32; ++j) {
            float w = W1s[j * 512 + k];
            acc = fmaf(xr[j], w, acc);
            if (j < 16) accp = fmaf(xr[16 + j], w, accp);
        }
        float s = 1.f / (1.f + expf(-acc));
        float h = fmaxf(acc, 0.f) + log1pf(expf(-fabsf(acc)));
        int gi = (b0 + b) * 512 + k;
        g_s1[gi] = s;
        g_h1[gi] = h;
        g_p[gi]  = accp;
    }
}

// ---------------- K2: z2 = h1@W2 + b2 -> d2,u2 ; fused v = (s1*p)@W2 -> w ----------------
__global__ __launch_bounds__(256) void k2_layer2(const float* __restrict__ W2,
                                                 const float* __restrict__ b2,
                                                 const float* __restrict__ W3) {
    __shared__ __align__(16) float As[64][17];
    __shared__ __align__(16) float As2[64][17];
    __shared__ __align__(16) float Bs[16][64];
    int tid = threadIdx.x;
    int b0 = blockIdx.x * 64;
    int m0 = blockIdx.y * 64;
    int ty = tid >> 4, tx = tid & 15;
    float acc[4][4] = {};
    float acc2[4][4] = {};

    for (int k0 = 0; k0 < HID; k0 += 16) {
        __syncthreads();
#pragma unroll
        for (int r = 0; r < 4; ++r) {
            int idx = tid + r * 256;
            int gi = (b0 + (idx >> 4)) * HID + k0 + (idx & 15);
            As[idx >> 4][idx & 15]  = g_h1[gi];
            As2[idx >> 4][idx & 15] = g_s1[gi] * g_p[gi];
        }
#pragma unroll
        for (int r = 0; r < 4; ++r) {
            int idx = tid + r * 256;
            Bs[idx >> 6][idx & 63] = W2[(k0 + (idx >> 6)) * HID + m0 + (idx & 63)];
        }
        __syncthreads();
#pragma unroll
        for (int kk = 0; kk < 16; ++kk) {
            float4 bv = *reinterpret_cast<const float4*>(&Bs[kk][tx * 4]);
#pragma unroll
            for (int i = 0; i < 4; ++i) {
                float a = As[ty * 4 + i][kk];
                acc[i][0] = fmaf(a, bv.x, acc[i][0]);
                acc[i][1] = fmaf(a, bv.y, acc[i][1]);
                acc[i][2] = fmaf(a, bv.z, acc[i][2]);
                acc[i][3] = fmaf(a, bv.w, acc[i][3]);
                float a2 = As2[ty * 4 + i][kk];
                acc2[i][0] = fmaf(a2, bv.x, acc2[i][0]);
                acc2[i][1] = fmaf(a2, bv.y, acc2[i][1]);
                acc2[i][2] = fmaf(a2, bv.z, acc2[i][2]);
                acc2[i][3] = fmaf(a2, bv.w, acc2[i][3]);
            }
        }
    }
#pragma unroll
    for (int i = 0; i < 4; ++i) {
        int b = b0 + ty * 4 + i;
#pragma unroll
        for (int j = 0; j < 4; ++j) {
            int m = m0 + tx * 4 + j;
            float z = acc[i][j] + b2[m];
            float s = 1.f / (1.f + expf(-z));
            float w3v = W3[m];
            float d2v = s * (1.f - s) * w3v;
            g_d2[b * HID + m] = d2v;
            g_u2[b * HID + m] = s * w3v;
            g_w [b * HID + m] = acc2[i][j] * d2v;
        }
    }
}

// ---------------- K3: g1 = u2 @ W2^T -> u1 (g_h1), d1 (g_g1) ----------------
__global__ __launch_bounds__(256) void k3_g1(const float* __restrict__ W2) {
    __shared__ float As[64][17];
    __shared__ float Bs[16][68];
    int tid = threadIdx.x;
    int b0  = blockIdx.x * 64;
    int k00 = blockIdx.y * 64;
    int ty = tid >> 4, tx = tid & 15;
    float acc[4][4] = {};

    for (int m0 = 0; m0 < HID; m0 += 16) {
        __syncthreads();
#pragma unroll
        for (int r = 0; r < 4; ++r) {
            int idx = tid + r * 256;
            As[idx >> 4][idx & 15] = g_u2[(b0 + (idx >> 4)) * HID + m0 + (idx & 15)];
        }
#pragma unroll
        for (int r = 0; r < 4; ++r) {
            int idx = tid + r * 256;
            Bs[idx & 15][idx >> 4] = W2[(k00 + (idx >> 4)) * HID + m0 + (idx & 15)];
        }
        __syncthreads();
#pragma unroll
        for (int mm = 0; mm < 16; ++mm) {
            float v0 = Bs[mm][tx * 4 + 0], v1 = Bs[mm][tx * 4 + 1];
            float v2 = Bs[mm][tx * 4 + 2], v3 = Bs[mm][tx * 4 + 3];
#pragma unroll
            for (int i = 0; i < 4; ++i) {
                float a = As[ty * 4 + i][mm];
                acc[i][0] = fmaf(a, v0, acc[i][0]);
                acc[i][1] = fmaf(a, v1, acc[i][1]);
                acc[i][2] = fmaf(a, v2, acc[i][2]);
                acc[i][3] = fmaf(a, v3, acc[i][3]);
            }
        }
    }
#pragma unroll
    for (int i = 0; i < 4; ++i) {
        int b = b0 + ty * 4 + i;
#pragma unroll
        for (int j = 0; j < 4; ++j) {
            int gi = b * HID + k00 + tx * 4 + j;
            float g = acc[i][j];
            float s = g_s1[gi];
            g_h1[gi] = s * g;                 // u1
            g_g1[gi] = s * (1.f - s) * g;     // d1
        }
    }
}

// ---------------- K_jac: rhs_base = jac_top - W1_lo*(d1*p) ----------------
#define KJ_SMEM (32 * 513 * 4)
__global__ __launch_bounds__(256) void k_jac(const float* __restrict__ W1) {
    extern __shared__ float W1s[];   // [j*513 + k]
    int tid = threadIdx.x;
    int b0  = blockIdx.x * 8;
    for (int idx = tid; idx < 32 * 512; idx += 256)
        W1s[(idx >> 9) * 513 + (idx & 511)] = W1[idx];
    __syncthreads();

    int s = tid >> 5, lane = tid & 31;
    int i = lane & 15, half = lane >> 4;
    int b = b0 + s;
    float accJ = 0.f, accR = 0.f;
    const float* u1p = g_h1 + (size_t)b * 512;
    const float* d1p = g_g1 + (size_t)b * 512;
    const float* pp  = g_p  + (size_t)b * 512;
    for (int t = 0; t < 256; ++t) {
        int k = half * 256 + t;
        accJ = fmaf(W1s[i * 513 + k], u1p[k], accJ);
        accR = fmaf(W1s[(16 + i) * 513 + k], d1p[k] * pp[k], accR);
    }
    accJ += __shfl_xor_sync(0xffffffffu, accJ, 16);
    accR += __shfl_xor_sync(0xffffffffu, accR, 16);
    if (lane < 16) g_rhs[(size_t)b * 16 + i] = accJ - accR;
}

// ---------------- K4a: Q_big = (s1 .* W1_lo) @ W2  — 128x128-tile SGEMM, f32x2 ----------------
// smem floats: W1s 512*17 | s1s 512*9 | As 16*132 | Bs 16*132
#define K4A_FLOATS (512*17 + 512*9 + 16*132 + 16*132)
#define K4A_SMEM   (K4A_FLOATS * 4)

__global__ __launch_bounds__(256, 2) void k4a_qgemm(const float* __restrict__ W1,
                                                    const float* __restrict__ W2) {
    extern __shared__ float sma[];
    float* W1s = sma;                 // [k*17 + i]   i in 0..15 (lo rows of W1)
    float* s1s = W1s + 512 * 17;      // [k*9 + s]    s in 0..7
    float* As  = s1s + 512 * 9;       // [kk*132 + row]
    float* Bs  = As + 16 * 132;       // [kk*132 + col]

    int tid = threadIdx.x;
    int r0 = blockIdx.x * 128;        // Q-row block (8 samples)
    int n0 = blockIdx.y * 128;        // column block
    int s0 = blockIdx.x * 8;
    int tx = tid & 15, ty = tid >> 4;

    for (int idx = tid; idx < 16 * 512; idx += 256) {
        int i = idx >> 9, k = idx & 511;
        W1s[k * 17 + i] = W1[(16 + i) * 512 + k];
    }
    for (int idx = tid; idx < 8 * 512; idx += 256) {
        int s = idx >> 9, k = idx & 511;
        s1s[k * 9 + s] = g_s1[(size_t)(s0 + s) * 512 + k];
    }

    unsigned long long acc[8][4] = {};

    for (int kt = 0; kt < 32; ++kt) {
        int k0 = kt * 16;
        __syncthreads();
#pragma unroll
        for (int it = 0; it < 8; ++it) {
            int idx = it * 256 + tid;
            int kk = idx >> 7, row = idx & 127;
            As[kk * 132 + row] = W1s[(k0 + kk) * 17 + (row & 15)] *
                                 s1s[(k0 + kk) * 9 + (row >> 4)];
        }
#pragma unroll
        for (int it = 0; it < 2; ++it) {
            int idx = it * 256 + tid;
            int kk = idx >> 5, c4 = idx & 31;
            *reinterpret_cast<float4*>(&Bs[kk * 132 + c4 * 4]) =
                *reinterpret_cast<const float4*>(&W2[(size_t)(k0 + kk) * 512 + n0 + c4 * 4]);
        }
        __syncthreads();
#pragma unroll
        for (int kk = 0; kk < 16; ++kk) {
            float4 a0 = *reinterpret_cast<const float4*>(&As[kk * 132 + ty * 8]);
            float4 a1 = *reinterpret_cast<const float4*>(&As[kk * 132 + ty * 8 + 4]);
            ulonglong2 b01 = *reinterpret_cast<const ulonglong2*>(&Bs[kk * 132 + tx * 8]);
            ulonglong2 b23 = *reinterpret_cast<const ulonglong2*>(&Bs[kk * 132 + tx * 8 + 4]);
            unsigned long long ap;
            ap = pack2(a0.x);
            fma2(acc[0][0], b01.x, ap); fma2(acc[0][1], b01.y, ap);
            fma2(acc[0][2], b23.x, ap); fma2(acc[0][3], b23.y, ap);
            ap = pack2(a0.y);
            fma2(acc[1][0], b01.x, ap); fma2(acc[1][1], b01.y, ap);
            fma2(acc[1][2], b23.x, ap); fma2(acc[1][3], b23.y, ap);
            ap = pack2(a0.z);
            fma2(acc[2][0], b01.x, ap); fma2(acc[2][1], b01.y, ap);
            fma2(acc[2][2], b23.x, ap); fma2(acc[2][3], b23.y, ap);
            ap = pack2(a0.w);
            fma2(acc[3][0], b01.x, ap); fma2(acc[3][1], b01.y, ap);
            fma2(acc[3][2], b23.x, ap); fma2(acc[3][3], b23.y, ap);
            ap = pack2(a1.x);
            fma2(acc[4][0], b01.x, ap); fma2(acc[4][1], b01.y, ap);
            fma2(acc[4][2], b23.x, ap); fma2(acc[4][3], b23.y, ap);
            ap = pack2(a1.y);
            fma2(acc[5][0], b01.x, ap); fma2(acc[5][1], b01.y, ap);
            fma2(acc[5][2], b23.x, ap); fma2(acc[5][3], b23.y, ap);
            ap = pack2(a1.z);
            fma2(acc[6][0], b01.x, ap); fma2(acc[6][1], b01.y, ap);
            fma2(acc[6][2], b23.x, ap); fma2(acc[6][3], b23.y, ap);
            ap = pack2(a1.w);
            fma2(acc[7][0], b01.x, ap); fma2(acc[7][1], b01.y, ap);
            fma2(acc[7][2], b23.x, ap); fma2(acc[7][3], b23.y, ap);
        }
    }

#pragma unroll
    for (int rr = 0; rr < 8; ++rr) {
        size_t row = (size_t)r0 + ty * 8 + rr;
        float* qp = g_Q + row * 512 + n0 + tx * 8;
        float2 f0 = unpack2(acc[rr][0]);
        float2 f1 = unpack2(acc[rr][1]);
        float2 f2 = unpack2(acc[rr][2]);
        float2 f3 = unpack2(acc[rr][3]);
        float4 v0; v0.x = f0.x; v0.y = f0.y; v0.z = f1.x; v0.w = f1.y;
        float4 v1; v1.x = f2.x; v1.y = f2.y; v1.z = f3.x; v1.w = f3.y;
        *reinterpret_cast<float4*>(qp)     = v0;
        *reinterpret_cast<float4*>(qp + 4) = v1;
    }
}

// ---------------- K4b: A = Q D2 Q^T + W1_lo D1 W1_lo^T ; rhs -= Q w ----------------
// smem floats: W1s 512*17 | Qc 128*68 | d1s 8*512 | d2c 8*64 | wc 8*64
#define K4B_FLOATS (512*17 + 128*68 + 8*512 + 8*64 + 8*64)
#define K4B_SMEM   (K4B_FLOATS * 4)

__global__ __launch_bounds__(256, 2) void k4b_assemble(const float* __restrict__ W1) {
    extern __shared__ float smb[];
    float* W1s = smb;                 // [k*17 + i]
    float* Qc  = W1s + 512 * 17;      // [(s*16+i)*68 + m]
    float* d1s = Qc + 128 * 68;       // [s*512 + k]
    float* d2c = d1s + 8 * 512;       // [s*64 + m]
    float* wc  = d2c + 8 * 64;        // [s*64 + m]

    int tid = threadIdx.x;
    int b0  = blockIdx.x * 8;

    for (int idx = tid; idx < 16 * 512; idx += 256) {
        int i = idx >> 9, k = idx & 511;
        W1s[k * 17 + i] = W1[(16 + i) * 512 + k];
    }
    for (int idx = tid; idx < 8 * 512; idx += 256)
        d1s[idx] = g_g1[(size_t)b0 * 512 + idx];

    int s = tid >> 5, lane = tid & 31;
    int rg = lane >> 3, cg = lane & 7;

    float A0[4] = {}, A1[4] = {}, rhs2[4] = {};

    for (int mc = 0; mc < 8; ++mc) {
        int m0 = mc * 64;
        __syncthreads();
#pragma unroll
        for (int it = 0; it < 8; ++it) {
            int idx = it * 256 + tid;
            int ss = idx >> 8, rem = idx & 255;
            int i = rem >> 4, c4 = rem & 15;
            *reinterpret_cast<float4*>(&Qc[(ss * 16 + i) * 68 + c4 * 4]) =
                *reinterpret_cast<const float4*>(&g_Q[((size_t)(b0 + ss) * 16 + i) * 512 + m0 + c4 * 4]);
        }
        for (int idx = tid; idx < 512; idx += 256) {
            int ss = idx >> 6, m = idx & 63;
            d2c[idx] = g_d2[(size_t)(b0 + ss) * 512 + m0 + m];
            wc[idx]  = g_w [(size_t)(b0 + ss) * 512 + m0 + m];
        }
        __syncthreads();

        const float* qb = Qc + s * 16 * 68;
        const float* dp = d2c + s * 64;
        const float* wp = wc + s * 64;
#pragma unroll 4
        for (int m = 0; m < 64; ++m) {
            float d2v = dp[m], wv = wp[m];
            float qj0 = qb[(2 * cg) * 68 + m];
            float qj1 = qb[(2 * cg + 1) * 68 + m];
#pragma unroll
            for (int rr = 0; rr < 4; ++rr) {
                float qi = qb[(4 * rg + rr) * 68 + m];
                float t = qi * d2v;
                A0[rr] = fmaf(t, qj0, A0[rr]);
                A1[rr] = fmaf(t, qj1, A1[rr]);
                rhs2[rr] = fmaf(qi, wv, rhs2[rr]);
            }
        }
    }

    // H1 term
    {
        const float* d1p = d1s + s * 512;
#pragma unroll 2
        for (int k = 0; k < 512; ++k) {
            float d1v = d1p[k];
            const float* wk = W1s + k * 17;
            float wj0 = wk[2 * cg], wj1 = wk[2 * cg + 1];
#pragma unroll
            for (int rr = 0; rr < 4; ++rr) {
                float t = wk[4 * rg + rr] * d1v;
                A0[rr] = fmaf(t, wj0, A0[rr]);
                A1[rr] = fmaf(t, wj1, A1[rr]);
            }
        }
    }

    int b = b0 + s;
#pragma unroll
    for (int rr = 0; rr < 4; ++rr) {
        int i = 4 * rg + rr;
        float* Ar = g_A + ((size_t)b * 16 + i) * 16;
        Ar[2 * cg]     = A0[rr];
        Ar[2 * cg + 1] = A1[rr];
        if (cg == 0) {
            size_t ob = (size_t)b * 16 + i;
            g_rhs[ob] -= rhs2[rr];
        }
    }
}

// ---------------- K5: per-sample symmetric Jacobi eigensolver + pinv semantics ----------------
#define PINV_RCOND 1.9073486e-5f
#define JACOBI_SWEEPS 8

__global__ __launch_bounds__(256) void k5_pinv(const float* __restrict__ x,
                                               float* __restrict__ out) {
    __shared__ float sm[16 * 592];
    int tid = threadIdx.x;
    int sI = tid >> 4;
    int r  = tid & 15;
    int b  = blockIdx.x * 16 + sI;

    float* As = sm + sI * 592;
    float* Vs = As + 272;
    float* ys = Vs + 272;
    float* rs = ys + 16;

    {
        const float* Ag = g_A + ((size_t)b * 16 + r) * 16;
#pragma unroll
        for (int j = 0; j < 16; ++j) {
            As[r * 17 + j] = Ag[j];
            Vs[r * 17 + j] = (r == j) ? 1.f : 0.f;
        }
        rs[r] = g_rhs[(size_t)b * 16 + r];
    }
    __syncwarp();

    for (int sweep = 0; sweep < JACOBI_SWEEPS; ++sweep) {
        for (int p = 0; p < 15; ++p) {
            for (int q = p + 1; q < 16; ++q) {
                float apq = As[p * 17 + q];
                float app = As[p * 17 + p];
                float aqq = As[q * 17 + q];
                float aip = As[r * 17 + p];
                float aiq = As[r * 17 + q];
                float vip = Vs[r * 17 + p];
                float viq = Vs[r * 17 + q];
                __syncwarp();
                float tau = (aqq - app) / (2.f * apq);
                float tt  = copysignf(1.f, tau) / (fabsf(tau) + sqrtf(fmaf(tau, tau, 1.f)));
                float t   = (fabsf(apq) > 0.f) ? tt : 0.f;
                float c   = 1.f / sqrtf(fmaf(t, t, 1.f));
                float s   = t * c;
                float nip = c * aip - s * aiq;
                float niq = s * aip + c * aiq;
                if (r != p && r != q) {
                    As[r * 17 + p] = nip; As[p * 17 + r] = nip;
                    As[r * 17 + q] = niq; As[q * 17 + r] = niq;
                }
                if (r == p) {
                    As[p * 17 + p] = app - t * apq;
                    As[q * 17 + q] = aqq + t * apq;
                    As[p * 17 + q] = 0.f;
                    As[q * 17 + p] = 0.f;
                }
                Vs[r * 17 + p] = c * vip - s * viq;
                Vs[r * 17 + q] = s * vip + c * viq;
                __syncwarp();
            }
        }
    }

    float lam = As[r * 17 + r];
    float m = fabsf(lam);
#pragma unroll
    for (int off = 8; off > 0; off >>= 1)
        m = fmaxf(m, __shfl_xor_sync(0xffffffffu, m, off));
    float cutoff = PINV_RCOND * m;

    float acc = 0.f;
#pragma unroll
    for (int j = 0; j < 16; ++j) acc = fmaf(Vs[j * 17 + r], rs[j], acc);
    ys[r] = (fabsf(lam) > cutoff) ? (acc / lam) : 0.f;
    __syncwarp();

    float qdd = 0.f;
#pragma unroll
    for (int j = 0; j < 16; ++j) qdd = fmaf(Vs[r * 17 + j], ys[j], qdd);

    out[(size_t)b * 32 + 16 + r] = qdd;
    out[(size_t)b * 32 + r]      = x[(size_t)b * 32 + 16 + r];
}

// ---------------- launch ----------------
extern "C" void kernel_launch(void* const* d_in, const int* in_sizes, int n_in,
                              void* d_out, int out_size) {
    const float* x  = (const float*)d_in[0];
    const float* W1 = (const float*)d_in[1];
    const float* b1 = (const float*)d_in[2];
    const float* W2 = (const float*)d_in[3];
    const float* b2 = (const float*)d_in[4];
    const float* W3 = (const float*)d_in[5];
    float* out = (float*)d_out;
    (void)in_sizes; (void)n_in; (void)out_size;

    cudaFuncSetAttribute(k1_layer1,    cudaFuncAttributeMaxDynamicSharedMemorySize, K1_SMEM);
    cudaFuncSetAttribute(k_jac,        cudaFuncAttributeMaxDynamicSharedMemorySize, KJ_SMEM);
    cudaFuncSetAttribute(k4a_qgemm,    cudaFuncAttributeMaxDynamicSharedMemorySize, K4A_SMEM);
    cudaFuncSetAttribute(k4b_assemble, cudaFuncAttributeMaxDynamicSharedMemorySize, K4B_SMEM);

    k1_layer1<<<BS / 8, 256, K1_SMEM>>>(x, W1, b1);
    k2_layer2<<<dim3(BS / 64, HID / 64), 256>>>(W2, b2, W3);
    k3_g1<<<dim3(BS / 64, HID / 64), 256>>>(W2);
    k_jac<<<BS / 8, 256, KJ_SMEM>>>(W1);
    k4a_qgemm<<<dim3(BS * 16 / 128, HID / 128), 256, K4A_SMEM>>>(W1, W2);
    k4b_assemble<<<BS / 8, 256, K4B_SMEM>>>(W1);
    k5_pinv<<<BS / 16, 256>>>(x, out);
}